// round 3
// baseline (speedup 1.0000x reference)
#include <cuda_runtime.h>
#include <math.h>

#define G 128
#define NODES 256
#define DFEAT 128
#define KB 16
#define PITCH 132          // 128 + 4 pad: float4 LDS at row-stride 132 -> 2-way conflicts only
#define NPAIR 65536        // 256*256

// Scratch (static device globals — no runtime allocation)
__device__ float g_D[256u * 65536u];   // 64 MB: D matrices, 256 graph-views
__device__ float g_part[512];          // per-block partial sums of D
__device__ float g_sig[256 * KB];      // signatures
__device__ float g_ntx[32];            // NT-Xent partials

__device__ __forceinline__ float warpSum(float v) {
#pragma unroll
    for (int o = 16; o > 0; o >>= 1) v += __shfl_down_sync(0xffffffffu, v, o);
    return v;
}

// ---------------------------------------------------------------------------
// Kernel A: per (graph-view, half) compute 128x256 block of the distance
// matrix D = sqrt(max(|hi|^2+|hj|^2-2 hi.hj, 0) + 1e-12), store to g_D,
// and write the block's partial sum of D to g_part[bid].
// grid = 512 (256 graph-views * 2 halves), block = 512 threads.
// ---------------------------------------------------------------------------
__global__ void __launch_bounds__(512, 1)
kA(const float* __restrict__ H1, const float* __restrict__ H2) {
    extern __shared__ float sm[];
    float* sH  = sm;                    // NODES * PITCH
    float* sSq = sm + NODES * PITCH;    // NODES
    float* sRed = sSq + NODES;          // 16

    int bid  = blockIdx.x;
    int gv   = bid >> 1;
    int half = bid & 1;
    const float* Hg = (gv < G) ? (H1 + (size_t)gv * NODES * DFEAT)
                               : (H2 + (size_t)(gv - G) * NODES * DFEAT);
    int tid = threadIdx.x;

    // cooperative load H (256x128 f32) into smem, float4, pitched
    for (int t = tid; t < NODES * (DFEAT / 4); t += 512) {
        int row = t >> 5, c4 = t & 31;
        float4 v = ((const float4*)Hg)[(size_t)row * (DFEAT / 4) + c4];
        *(float4*)(sH + row * PITCH + c4 * 4) = v;
    }
    __syncthreads();

    if (tid < NODES) {
        const float* r = sH + tid * PITCH;
        float s = 0.f;
#pragma unroll 8
        for (int k = 0; k < DFEAT; k++) s += r[k] * r[k];
        sSq[tid] = s;
    }
    __syncthreads();

    int ty = tid >> 5, lane = tid & 31;
    int i0 = half * 128 + ty * 8;       // 16 ty * 8 rows = 128 rows

    float acc[8][8];
#pragma unroll
    for (int a = 0; a < 8; a++)
#pragma unroll
        for (int b = 0; b < 8; b++) acc[a][b] = 0.f;

    for (int k = 0; k < DFEAT; k += 4) {
        float4 av[8];
#pragma unroll
        for (int ii = 0; ii < 8; ii++)
            av[ii] = *(const float4*)(sH + (i0 + ii) * PITCH + k);
#pragma unroll
        for (int s = 0; s < 8; s++) {
            float4 bv = *(const float4*)(sH + (lane + 32 * s) * PITCH + k);
#pragma unroll
            for (int ii = 0; ii < 8; ii++) {
                acc[ii][s] = fmaf(av[ii].x, bv.x, acc[ii][s]);
                acc[ii][s] = fmaf(av[ii].y, bv.y, acc[ii][s]);
                acc[ii][s] = fmaf(av[ii].z, bv.z, acc[ii][s]);
                acc[ii][s] = fmaf(av[ii].w, bv.w, acc[ii][s]);
            }
        }
    }

    float lsum = 0.f;
    float* Dout = g_D + (size_t)gv * NPAIR;
#pragma unroll
    for (int ii = 0; ii < 8; ii++) {
        int i = i0 + ii;
        float sqi = sSq[i];
#pragma unroll
        for (int s = 0; s < 8; s++) {
            int j = lane + 32 * s;
            float d2 = sqi + sSq[j] - 2.f * acc[ii][s];
            float d = sqrtf(fmaxf(d2, 0.f) + 1e-12f);
            Dout[i * NODES + j] = d;
            lsum += d;
        }
    }

    lsum = warpSum(lsum);
    if (lane == 0) sRed[ty] = lsum;
    __syncthreads();
    if (tid < 32) {
        float v = (tid < 16) ? sRed[tid] : 0.f;
        v = warpSum(v);
        if (tid == 0) g_part[bid] = v;
    }
}

// ---------------------------------------------------------------------------
// Kernel B: per graph-view, normalize D by its mean, accumulate 16-bin soft
// histogram (Gaussian kernels), normalize to a signature.
// grid = 256, block = 512.
// ---------------------------------------------------------------------------
__global__ void __launch_bounds__(512)
kB() {
    __shared__ float sh[KB + 1];
    int gv = blockIdx.x, tid = threadIdx.x;
    if (tid <= KB) sh[tid] = 0.f;
    __syncthreads();

    float mean = (g_part[2 * gv] + g_part[2 * gv + 1]) * (1.0f / 65536.0f);
    float invm = 1.0f / (mean + 1e-8f);
    const float* Dp = g_D + (size_t)gv * NPAIR;

    float h[KB];
#pragma unroll
    for (int k = 0; k < KB; k++) h[k] = 0.f;

    const float invsig = 16.0f / 3.0f;   // 1/sigma, sigma = BIN_MAX/K
    for (int idx = tid; idx < NPAIR; idx += 512) {
        float dn = Dp[idx] * invm;
        float u = dn * invsig;
#pragma unroll
        for (int k = 0; k < KB; k++) {
            float t = u - (0.2f * invsig) * (float)k;   // (dn - 0.2k)/sigma
            h[k] += __expf(-0.5f * t * t);
        }
    }

#pragma unroll
    for (int k = 0; k < KB; k++) {
        float v = warpSum(h[k]);
        if ((tid & 31) == 0) atomicAdd(&sh[k], v);
    }
    __syncthreads();
    if (tid == 0) {
        float S = 0.f;
        for (int k = 0; k < KB; k++) S += sh[k];
        sh[KB] = S;
    }
    __syncthreads();
    if (tid < KB) g_sig[gv * KB + tid] = sh[tid] / (sh[KB] + 1e-8f);
}

// ---------------------------------------------------------------------------
// Kernel C: NT-Xent. grid = 32 blocks, each handles 8 rows of the 256-row
// similarity problem. block = 256 threads; each block normalizes the full z
// locally (cheap) so rows can dot against everything from smem.
// ---------------------------------------------------------------------------
__global__ void __launch_bounds__(256, 1)
kC(const float* __restrict__ z1, const float* __restrict__ z2) {
    extern __shared__ float sm[];
    float* zn = sm;                 // 256 * PITCH
    float* sRed = sm + 256 * PITCH; // 8

    int tid = threadIdx.x;
    for (int t = tid; t < 2 * G * DFEAT; t += 256) {
        int row = t >> 7, k = t & 127;
        float v = (row < G) ? z1[t] : z2[t - G * DFEAT];
        zn[row * PITCH + k] = v;
    }
    __syncthreads();
    {
        int row = tid;  // exactly 256 rows
        float* r = zn + row * PITCH;
        float s = 0.f;
#pragma unroll 8
        for (int k = 0; k < DFEAT; k++) s += r[k] * r[k];
        float inv = 1.0f / (sqrtf(s) + 1e-8f);
#pragma unroll 8
        for (int k = 0; k < DFEAT; k++) r[k] *= inv;
    }
    __syncthreads();

    int w = tid >> 5, lane = tid & 31;
    int i = blockIdx.x * 8 + w;                 // row this warp owns
    int label = (i < G) ? i + G : i - G;
    const float* zi = zn + i * PITCH;

    float sims[8];
#pragma unroll
    for (int s = 0; s < 8; s++) {
        int j = lane + 32 * s;
        const float* zj = zn + j * PITCH;
        float acc = 0.f;
        for (int k = 0; k < DFEAT; k += 4) {
            float4 a = *(const float4*)(zi + k);
            float4 b = *(const float4*)(zj + k);
            acc = fmaf(a.x, b.x, acc);
            acc = fmaf(a.y, b.y, acc);
            acc = fmaf(a.z, b.z, acc);
            acc = fmaf(a.w, b.w, acc);
        }
        float sim = acc * 2.0f;                 // 1/TEMP = 2
        if (j == i) sim = -1e9f;
        sims[s] = sim;
    }

    float m = -1e30f, slab = 0.f;
#pragma unroll
    for (int s = 0; s < 8; s++) {
        m = fmaxf(m, sims[s]);
        if (lane + 32 * s == label) slab = sims[s];
    }
#pragma unroll
    for (int o = 16; o > 0; o >>= 1)
        m = fmaxf(m, __shfl_xor_sync(0xffffffffu, m, o));

    float se = 0.f;
#pragma unroll
    for (int s = 0; s < 8; s++) se += __expf(sims[s] - m);
    se = warpSum(se);
    slab = warpSum(slab);

    if (lane == 0) sRed[w] = (m + logf(se)) - slab;  // logsumexp - sim[label]
    __syncthreads();
    if (tid == 0) {
        float t = 0.f;
        for (int s = 0; s < 8; s++) t += sRed[s];
        g_ntx[blockIdx.x] = t;
    }
}

// ---------------------------------------------------------------------------
// Kernel D: combine topo MSE + NT-Xent into the scalar loss.
// ---------------------------------------------------------------------------
__global__ void kD(float* out) {
    __shared__ float sRed[4];
    int tid = threadIdx.x;  // 128
    int w = tid >> 5, lane = tid & 31;

    float t = 0.f;
    {
        const float* a = g_sig + tid * KB;
        const float* b = g_sig + (G + tid) * KB;
#pragma unroll
        for (int k = 0; k < KB; k++) {
            float d = a[k] - b[k];
            t += d * d;
        }
        t *= (1.0f / KB);
    }
    t = warpSum(t);
    if (lane == 0) sRed[w] = t;
    __syncthreads();

    float ntx = 0.f;
    if (tid < 32) ntx = g_ntx[tid];
    ntx = warpSum(ntx);

    if (tid == 0) {
        float topo = (sRed[0] + sRed[1] + sRed[2] + sRed[3]) * (1.0f / G);
        out[0] = 0.1f * (topo + ntx * (1.0f / 256.0f));
    }
}

// ---------------------------------------------------------------------------
extern "C" void kernel_launch(void* const* d_in, const int* in_sizes, int n_in,
                              void* d_out, int out_size) {
    const float* H1 = (const float*)d_in[0];
    // d_in[1], d_in[3] are batch indices (int64) — graphs are contiguous equal-size, unused
    const float* H2 = (const float*)d_in[2];
    const float* z1 = (const float*)d_in[4];
    const float* z2 = (const float*)d_in[5];

    size_t smA = (size_t)(NODES * PITCH + NODES + 32) * sizeof(float);
    size_t smC = (size_t)(256 * PITCH + 32) * sizeof(float);
    cudaFuncSetAttribute(kA, cudaFuncAttributeMaxDynamicSharedMemorySize, (int)smA);
    cudaFuncSetAttribute(kC, cudaFuncAttributeMaxDynamicSharedMemorySize, (int)smC);

    kA<<<512, 512, smA>>>(H1, H2);
    kB<<<256, 512>>>();
    kC<<<32, 256, smC>>>(z1, z2);
    kD<<<1, 128>>>((float*)d_out);
}

// round 4
// speedup vs baseline: 3.1053x; 3.1053x over previous
#include <cuda_runtime.h>
#include <cuda_bf16.h>
#include <math.h>

#define G 128
#define NODES 256
#define DFEAT 128
#define KB 16
#define PITCHC 132           // fp32 pitch for kC smem

// H bf16 pitch (elements): 136 -> 272B row stride, conflict-free ldmatrix
#define PH 136
// D bf16 pitch (elements): 264 -> 528B row stride, conflict-free STS.32
#define PD 264

// smem byte offsets for fused kernel
#define OFF_H    0
#define OFF_D    69632                    // 256*136*2
#define OFF_SQ   (OFF_D + 135168)        // 256*264*2 -> 204800
#define OFF_RED  (OFF_SQ + 1024)         // float[32]
#define OFF_HIST (OFF_RED + 128)         // float[16*16 + 16 + 2]
#define SMEM_AB  (OFF_HIST + 4 * (256 + 16 + 2) + 16)

// factorized-exp constants: sigma = 3/16, alpha = 0.5/sigma^2 = 128/9
#define C_ALPHA   14.2222222f            // 128/9
#define C_LIN     5.68888889f            // 256/45
#define C_OFF     0.56888889f            // 128/225
#define C_C1      0.32052948f            // exp(-256/225)
#define C_C3      0.03293272f            // c^3
#define C_C4      0.01055548f            // c^4

__device__ float g_sig[256 * KB];
__device__ float g_ntx[32];

__device__ __forceinline__ float warpSum(float v) {
#pragma unroll
    for (int o = 16; o > 0; o >>= 1) v += __shfl_down_sync(0xffffffffu, v, o);
    return v;
}

// ---- packed f32x2 helpers (Blackwell) ----
__device__ __forceinline__ unsigned long long pk2(float a, float b) {
    unsigned long long r;
    asm("mov.b64 %0, {%1, %2};" : "=l"(r) : "f"(a), "f"(b));
    return r;
}
__device__ __forceinline__ void upk2(unsigned long long v, float& a, float& b) {
    asm("mov.b64 {%0, %1}, %2;" : "=f"(a), "=f"(b) : "l"(v));
}
__device__ __forceinline__ unsigned long long mul2(unsigned long long a, unsigned long long b) {
    unsigned long long r;
    asm("mul.rn.f32x2 %0, %1, %2;" : "=l"(r) : "l"(a), "l"(b));
    return r;
}
__device__ __forceinline__ unsigned long long add2(unsigned long long a, unsigned long long b) {
    unsigned long long r;
    asm("add.rn.f32x2 %0, %1, %2;" : "=l"(r) : "l"(a), "l"(b));
    return r;
}

__device__ __forceinline__ void ldsm_x4(unsigned smaddr, unsigned& r0, unsigned& r1,
                                        unsigned& r2, unsigned& r3) {
    asm volatile("ldmatrix.sync.aligned.m8n8.x4.shared.b16 {%0,%1,%2,%3}, [%4];"
                 : "=r"(r0), "=r"(r1), "=r"(r2), "=r"(r3) : "r"(smaddr));
}
__device__ __forceinline__ void mma_bf16(float& c0, float& c1, float& c2, float& c3,
                                         unsigned a0, unsigned a1, unsigned a2, unsigned a3,
                                         unsigned b0, unsigned b1) {
    asm volatile("mma.sync.aligned.m16n8k16.row.col.f32.bf16.bf16.f32 "
                 "{%0,%1,%2,%3}, {%4,%5,%6,%7}, {%8,%9}, {%0,%1,%2,%3};"
                 : "+f"(c0), "+f"(c1), "+f"(c2), "+f"(c3)
                 : "r"(a0), "r"(a1), "r"(a2), "r"(a3), "r"(b0), "r"(b1));
}

// ---------------------------------------------------------------------------
// Fused kernel: per graph-view (256 blocks x 512 threads):
//   1. load H -> bf16 smem
//   2. Gram via mma.sync bf16, D = sqrt(...) -> bf16 smem, accumulate sum(D)
//   3. factorized-exp soft histogram over D/mean -> signature g_sig
// ---------------------------------------------------------------------------
__global__ void __launch_bounds__(512, 1)
kAB(const float* __restrict__ H1, const float* __restrict__ H2) {
    extern __shared__ char sm[];
    __nv_bfloat16* sH = (__nv_bfloat16*)(sm + OFF_H);
    float* sSq   = (float*)(sm + OFF_SQ);
    float* sRed  = (float*)(sm + OFF_RED);
    float* sHist = (float*)(sm + OFF_HIST);

    const unsigned smBase = (unsigned)__cvta_generic_to_shared(sm);
    const unsigned sHb = smBase + OFF_H;
    const unsigned sDb = smBase + OFF_D;

    int gv  = blockIdx.x;
    int tid = threadIdx.x;
    int w = tid >> 5, lane = tid & 31;
    const float* Hg = (gv < G) ? (H1 + (size_t)gv * NODES * DFEAT)
                               : (H2 + (size_t)(gv - G) * NODES * DFEAT);

    // ---- load H, convert to bf16 (pitched) ----
    for (int t = tid; t < NODES * (DFEAT / 4); t += 512) {
        int row = t >> 5, c4 = t & 31;
        float4 v = ((const float4*)Hg)[(size_t)row * (DFEAT / 4) + c4];
        __nv_bfloat162 b01 = __floats2bfloat162_rn(v.x, v.y);
        __nv_bfloat162 b23 = __floats2bfloat162_rn(v.z, v.w);
        uint2 u;
        u.x = *(unsigned*)&b01;
        u.y = *(unsigned*)&b23;
        *(uint2*)(sm + OFF_H + (row * PH + c4 * 4) * 2) = u;
    }
    __syncthreads();

    // ---- row norms from bf16 values (keeps Gram diagonal ~0) ----
    if (tid < NODES) {
        const __nv_bfloat162* r = (const __nv_bfloat162*)(sH + tid * PH);
        float s = 0.f;
#pragma unroll 8
        for (int k = 0; k < DFEAT / 2; k++) {
            float2 f = __bfloat1622float2(r[k]);
            s = fmaf(f.x, f.x, s);
            s = fmaf(f.y, f.y, s);
        }
        sSq[tid] = s;
    }
    __syncthreads();

    // ---- Gram via tensor cores: warp w owns rows [w*16, w*16+16) ----
    int i0 = w * 16;
    // unified ldmatrix address pattern: lanes 0-15 -> row base+(l&15) col k0,
    // lanes 16-31 -> row base+(l&15) col k0+8
    int lrow = lane & 15;
    int lcol8 = (lane >> 4) << 3;

    unsigned a[8][4];
#pragma unroll
    for (int kc = 0; kc < 8; kc++) {
        unsigned ad = sHb + 2u * ((i0 + lrow) * PH + kc * 16 + lcol8);
        ldsm_x4(ad, a[kc][0], a[kc][1], a[kc][2], a[kc][3]);
    }

    int gq = lane >> 2;        // 0..7
    int tq = lane & 3;         // 0..3
    float dsum = 0.f;

    for (int j0 = 0; j0 < NODES; j0 += 16) {
        float c0[4] = {0.f, 0.f, 0.f, 0.f};
        float c1[4] = {0.f, 0.f, 0.f, 0.f};
#pragma unroll
        for (int kc = 0; kc < 8; kc++) {
            unsigned bd = sHb + 2u * ((j0 + lrow) * PH + kc * 16 + lcol8);
            unsigned b0, b1, b2, b3;
            ldsm_x4(bd, b0, b1, b2, b3);
            mma_bf16(c0[0], c0[1], c0[2], c0[3], a[kc][0], a[kc][1], a[kc][2], a[kc][3], b0, b2);
            mma_bf16(c1[0], c1[1], c1[2], c1[3], a[kc][0], a[kc][1], a[kc][2], a[kc][3], b1, b3);
        }
        // epilogue: d = sqrt(max(sqi+sqj-2g,0)+1e-12); bf16x2 store; sum
#pragma unroll
        for (int t2 = 0; t2 < 2; t2++) {
            const float* cc = t2 ? c1 : c0;
            int jc = j0 + t2 * 8 + 2 * tq;
            float sqj0 = sSq[jc], sqj1 = sSq[jc + 1];
#pragma unroll
            for (int rh = 0; rh < 2; rh++) {
                int r = i0 + gq + rh * 8;
                float sqi = sSq[r];
                float da = sqrtf(fmaxf(fmaf(-2.f, cc[rh * 2 + 0], sqi + sqj0), 0.f) + 1e-12f);
                float db = sqrtf(fmaxf(fmaf(-2.f, cc[rh * 2 + 1], sqi + sqj1), 0.f) + 1e-12f);
                dsum += da + db;
                __nv_bfloat162 dd = __floats2bfloat162_rn(da, db);
                *(unsigned*)(sm + OFF_D + (r * PD + jc) * 2) = *(unsigned*)&dd;
            }
        }
    }

    dsum = warpSum(dsum);
    if (lane == 0) sRed[w] = dsum;
    __syncthreads();
    if (tid == 0) {
        float tot = 0.f;
#pragma unroll
        for (int i = 0; i < 16; i++) tot += sRed[i];
        float mean = tot * (1.0f / 65536.0f);
        sHist[256 + 16] = 1.0f / (mean + 1e-8f);
    }
    __syncthreads();
    float invm = sHist[256 + 16];

    // ---- factorized-exp histogram ----
    unsigned long long Hc[8];
#pragma unroll
    for (int p = 0; p < 8; p++) Hc[p] = pk2(0.f, 0.f);
    const unsigned long long C4p = pk2(C_C4, C_C4);

    for (int idx2 = tid; idx2 < 32768; idx2 += 512) {
        int row = idx2 >> 7, cp = idx2 & 127;
        unsigned u = *(unsigned*)(sm + OFF_D + row * (PD * 2) + cp * 4);
        __nv_bfloat162 bb = *(__nv_bfloat162*)&u;
        float2 dv = __bfloat1622float2(bb);
#pragma unroll
        for (int e = 0; e < 2; e++) {
            float x = fminf((e ? dv.y : dv.x) * invm, 2.46f);
            float w0 = __expf(-C_ALPHA * x * x);
            float r0 = __expf(fmaf(C_LIN, x, -C_OFF));
            float w1 = w0 * r0;
            float r2 = r0 * r0;
            unsigned long long W = pk2(w0, w1);
            unsigned long long M = pk2(r2 * C_C1, r2 * C_C3);
            Hc[0] = add2(Hc[0], W);
#pragma unroll
            for (int p = 1; p < 8; p++) {
                W = mul2(W, M);
                M = mul2(M, C4p);
                Hc[p] = add2(Hc[p], W);
            }
        }
    }

    // reduce 16 bins: warp-reduce, then cross-warp fixed-order sum
    float hl[16];
#pragma unroll
    for (int p = 0; p < 8; p++) upk2(Hc[p], hl[2 * p], hl[2 * p + 1]);
#pragma unroll
    for (int k = 0; k < 16; k++) {
        float v = warpSum(hl[k]);
        if (lane == 0) sHist[w * 16 + k] = v;
    }
    __syncthreads();
    if (tid < 16) {
        float s = 0.f;
#pragma unroll
        for (int ww = 0; ww < 16; ww++) s += sHist[ww * 16 + tid];
        sHist[256 + tid] = s;
    }
    __syncthreads();
    if (tid == 0) {
        float S = 0.f;
#pragma unroll
        for (int k = 0; k < 16; k++) S += sHist[256 + k];
        sHist[256 + 17] = 1.0f / (S + 1e-8f);
    }
    __syncthreads();
    if (tid < 16) g_sig[gv * KB + tid] = sHist[256 + tid] * sHist[256 + 17];
}

// ---------------------------------------------------------------------------
// NT-Xent: 32 blocks x 8 rows (unchanged from passing R1 kernel)
// ---------------------------------------------------------------------------
__global__ void __launch_bounds__(256, 1)
kC(const float* __restrict__ z1, const float* __restrict__ z2) {
    extern __shared__ float smf[];
    float* zn = smf;
    float* sRed = smf + 256 * PITCHC;

    int tid = threadIdx.x;
    for (int t = tid; t < 2 * G * DFEAT; t += 256) {
        int row = t >> 7, k = t & 127;
        float v = (row < G) ? z1[t] : z2[t - G * DFEAT];
        zn[row * PITCHC + k] = v;
    }
    __syncthreads();
    {
        int row = tid;
        float* r = zn + row * PITCHC;
        float s = 0.f;
#pragma unroll 8
        for (int k = 0; k < DFEAT; k++) s += r[k] * r[k];
        float inv = 1.0f / (sqrtf(s) + 1e-8f);
#pragma unroll 8
        for (int k = 0; k < DFEAT; k++) r[k] *= inv;
    }
    __syncthreads();

    int w = tid >> 5, lane = tid & 31;
    int i = blockIdx.x * 8 + w;
    int label = (i < G) ? i + G : i - G;
    const float* zi = zn + i * PITCHC;

    float sims[8];
#pragma unroll
    for (int s = 0; s < 8; s++) {
        int j = lane + 32 * s;
        const float* zj = zn + j * PITCHC;
        float acc = 0.f;
        for (int k = 0; k < DFEAT; k += 4) {
            float4 a = *(const float4*)(zi + k);
            float4 b = *(const float4*)(zj + k);
            acc = fmaf(a.x, b.x, acc);
            acc = fmaf(a.y, b.y, acc);
            acc = fmaf(a.z, b.z, acc);
            acc = fmaf(a.w, b.w, acc);
        }
        float sim = acc * 2.0f;
        if (j == i) sim = -1e9f;
        sims[s] = sim;
    }

    float m = -1e30f, slab = 0.f;
#pragma unroll
    for (int s = 0; s < 8; s++) {
        m = fmaxf(m, sims[s]);
        if (lane + 32 * s == label) slab = sims[s];
    }
#pragma unroll
    for (int o = 16; o > 0; o >>= 1)
        m = fmaxf(m, __shfl_xor_sync(0xffffffffu, m, o));

    float se = 0.f;
#pragma unroll
    for (int s = 0; s < 8; s++) se += __expf(sims[s] - m);
    se = warpSum(se);
    slab = warpSum(slab);

    if (lane == 0) sRed[w] = (m + logf(se)) - slab;
    __syncthreads();
    if (tid == 0) {
        float t = 0.f;
        for (int s = 0; s < 8; s++) t += sRed[s];
        g_ntx[blockIdx.x] = t;
    }
}

// ---------------------------------------------------------------------------
__global__ void kD(float* out) {
    __shared__ float sRed[4];
    int tid = threadIdx.x;
    int w = tid >> 5, lane = tid & 31;

    float t = 0.f;
    {
        const float* a = g_sig + tid * KB;
        const float* b = g_sig + (G + tid) * KB;
#pragma unroll
        for (int k = 0; k < KB; k++) {
            float d = a[k] - b[k];
            t += d * d;
        }
        t *= (1.0f / KB);
    }
    t = warpSum(t);
    if (lane == 0) sRed[w] = t;
    __syncthreads();

    float ntx = 0.f;
    if (tid < 32) ntx = g_ntx[tid];
    ntx = warpSum(ntx);

    if (tid == 0) {
        float topo = (sRed[0] + sRed[1] + sRed[2] + sRed[3]) * (1.0f / G);
        out[0] = 0.1f * (topo + ntx * (1.0f / 256.0f));
    }
}

// ---------------------------------------------------------------------------
extern "C" void kernel_launch(void* const* d_in, const int* in_sizes, int n_in,
                              void* d_out, int out_size) {
    const float* H1 = (const float*)d_in[0];
    const float* H2 = (const float*)d_in[2];
    const float* z1 = (const float*)d_in[4];
    const float* z2 = (const float*)d_in[5];

    size_t smAB = SMEM_AB;
    size_t smC = (size_t)(256 * PITCHC + 32) * sizeof(float);
    cudaFuncSetAttribute(kAB, cudaFuncAttributeMaxDynamicSharedMemorySize, (int)smAB);
    cudaFuncSetAttribute(kC, cudaFuncAttributeMaxDynamicSharedMemorySize, (int)smC);

    kAB<<<256, 512, smAB>>>(H1, H2);
    kC<<<32, 256, smC>>>(z1, z2);
    kD<<<1, 128>>>((float*)d_out);
}

// round 5
// speedup vs baseline: 3.9977x; 1.2874x over previous
#include <cuda_runtime.h>
#include <cuda_bf16.h>
#include <math.h>

#define G 128
#define NODES 256
#define DFEAT 128
#define KB 16
#define PITCHC 132           // fp32 pitch for kC smem

// H bf16 pitch (elements): 136 -> 272B row stride, conflict-free ldmatrix
#define PH 136
// D bf16 pitch (elements): 264 -> 528B row stride
#define PD 264

// smem byte offsets for fused kernel
#define OFF_H    0
#define OFF_D    69632                    // 256*136*2
#define OFF_SQ   (OFF_D + 135168)        // 256*264*2 -> 204800
#define OFF_RED  (OFF_SQ + 1024)         // float[32]
#define OFF_HIST (OFF_RED + 128)         // float[16*16 + 16 + 2]
#define SMEM_AB  (OFF_HIST + 4 * (256 + 16 + 2) + 16)

// factorized-exp constants: sigma = 3/16, alpha = 0.5/sigma^2 = 128/9
#define C_C1      0.32052948f            // exp(-256/225)
#define C_C3      0.03293272f            // c^3
#define C_C4      0.01055548f            // c^4
// log2e-folded: w0 = exp2(K_W*x^2), r0 = exp2(K_L*x + K_O)
#define K_W     (-20.5183296f)           // -(128/9)*log2(e)
#define K_L       8.2073318f             // (256/45)*log2(e)
#define K_O      (-0.82073318f)          // -(128/225)*log2(e)

__device__ float g_sig[256 * KB];
__device__ float g_ntx[32];

// 136 upper-triangle tiles, packed (ti<<4)|tj
__constant__ unsigned char c_tile[136] = {
    0x00,0x01,0x02,0x03,0x04,0x05,0x06,0x07,0x08,0x09,0x0A,0x0B,0x0C,0x0D,0x0E,0x0F,
    0x11,0x12,0x13,0x14,0x15,0x16,0x17,0x18,0x19,0x1A,0x1B,0x1C,0x1D,0x1E,0x1F,
    0x22,0x23,0x24,0x25,0x26,0x27,0x28,0x29,0x2A,0x2B,0x2C,0x2D,0x2E,0x2F,
    0x33,0x34,0x35,0x36,0x37,0x38,0x39,0x3A,0x3B,0x3C,0x3D,0x3E,0x3F,
    0x44,0x45,0x46,0x47,0x48,0x49,0x4A,0x4B,0x4C,0x4D,0x4E,0x4F,
    0x55,0x56,0x57,0x58,0x59,0x5A,0x5B,0x5C,0x5D,0x5E,0x5F,
    0x66,0x67,0x68,0x69,0x6A,0x6B,0x6C,0x6D,0x6E,0x6F,
    0x77,0x78,0x79,0x7A,0x7B,0x7C,0x7D,0x7E,0x7F,
    0x88,0x89,0x8A,0x8B,0x8C,0x8D,0x8E,0x8F,
    0x99,0x9A,0x9B,0x9C,0x9D,0x9E,0x9F,
    0xAA,0xAB,0xAC,0xAD,0xAE,0xAF,
    0xBB,0xBC,0xBD,0xBE,0xBF,
    0xCC,0xCD,0xCE,0xCF,
    0xDD,0xDE,0xDF,
    0xEE,0xEF,
    0xFF
};

__device__ __forceinline__ float warpSum(float v) {
#pragma unroll
    for (int o = 16; o > 0; o >>= 1) v += __shfl_down_sync(0xffffffffu, v, o);
    return v;
}

// ---- packed f32x2 helpers (Blackwell) ----
__device__ __forceinline__ unsigned long long pk2(float a, float b) {
    unsigned long long r;
    asm("mov.b64 %0, {%1, %2};" : "=l"(r) : "f"(a), "f"(b));
    return r;
}
__device__ __forceinline__ void upk2(unsigned long long v, float& a, float& b) {
    asm("mov.b64 {%0, %1}, %2;" : "=f"(a), "=f"(b) : "l"(v));
}
__device__ __forceinline__ unsigned long long mul2(unsigned long long a, unsigned long long b) {
    unsigned long long r;
    asm("mul.rn.f32x2 %0, %1, %2;" : "=l"(r) : "l"(a), "l"(b));
    return r;
}
__device__ __forceinline__ unsigned long long add2(unsigned long long a, unsigned long long b) {
    unsigned long long r;
    asm("add.rn.f32x2 %0, %1, %2;" : "=l"(r) : "l"(a), "l"(b));
    return r;
}

__device__ __forceinline__ void ldsm_x4(unsigned smaddr, unsigned& r0, unsigned& r1,
                                        unsigned& r2, unsigned& r3) {
    asm volatile("ldmatrix.sync.aligned.m8n8.x4.shared.b16 {%0,%1,%2,%3}, [%4];"
                 : "=r"(r0), "=r"(r1), "=r"(r2), "=r"(r3) : "r"(smaddr));
}
__device__ __forceinline__ void mma_bf16(float& c0, float& c1, float& c2, float& c3,
                                         unsigned a0, unsigned a1, unsigned a2, unsigned a3,
                                         unsigned b0, unsigned b1) {
    asm volatile("mma.sync.aligned.m16n8k16.row.col.f32.bf16.bf16.f32 "
                 "{%0,%1,%2,%3}, {%4,%5,%6,%7}, {%8,%9}, {%0,%1,%2,%3};"
                 : "+f"(c0), "+f"(c1), "+f"(c2), "+f"(c3)
                 : "r"(a0), "r"(a1), "r"(a2), "r"(a3), "r"(b0), "r"(b1));
}

// packed bins-in-lanes accumulate of one pair (weight 1)
__device__ __forceinline__ void accum_packed(float x, unsigned long long* Hc,
                                             unsigned long long C4p) {
    float w0 = exp2f(K_W * x * x);
    float r0 = exp2f(fmaf(K_L, x, K_O));
    float w1 = w0 * r0;
    float r2 = r0 * r0;
    unsigned long long W = pk2(w0, w1);
    unsigned long long M = pk2(r2 * C_C1, r2 * C_C3);
    Hc[0] = add2(Hc[0], W);
#pragma unroll
    for (int p = 1; p < 8; p++) {
        W = mul2(W, M);
        M = mul2(M, C4p);
        Hc[p] = add2(Hc[p], W);
    }
}

// ---------------------------------------------------------------------------
// Fused kernel: per graph-view (256 blocks x 512 threads):
//   1. load H -> bf16 smem
//   2. upper-triangle Gram tiles via mma.sync bf16; D -> bf16 smem; weighted sum(D)
//   3. factorized-exp soft histogram over upper triangle (x2) + diagonal (x1)
// ---------------------------------------------------------------------------
__global__ void __launch_bounds__(512, 1)
kAB(const float* __restrict__ H1, const float* __restrict__ H2) {
    extern __shared__ char sm[];
    __nv_bfloat16* sH = (__nv_bfloat16*)(sm + OFF_H);
    float* sSq   = (float*)(sm + OFF_SQ);
    float* sRed  = (float*)(sm + OFF_RED);
    float* sHist = (float*)(sm + OFF_HIST);

    const unsigned smBase = (unsigned)__cvta_generic_to_shared(sm);
    const unsigned sHb = smBase + OFF_H;

    int gv  = blockIdx.x;
    int tid = threadIdx.x;
    int w = tid >> 5, lane = tid & 31;
    const float* Hg = (gv < G) ? (H1 + (size_t)gv * NODES * DFEAT)
                               : (H2 + (size_t)(gv - G) * NODES * DFEAT);

    // ---- load H, convert to bf16 (pitched) ----
    for (int t = tid; t < NODES * (DFEAT / 4); t += 512) {
        int row = t >> 5, c4 = t & 31;
        float4 v = ((const float4*)Hg)[(size_t)row * (DFEAT / 4) + c4];
        __nv_bfloat162 b01 = __floats2bfloat162_rn(v.x, v.y);
        __nv_bfloat162 b23 = __floats2bfloat162_rn(v.z, v.w);
        uint2 u;
        u.x = *(unsigned*)&b01;
        u.y = *(unsigned*)&b23;
        *(uint2*)(sm + OFF_H + (row * PH + c4 * 4) * 2) = u;
    }
    __syncthreads();

    // ---- row norms from bf16 values ----
    if (tid < NODES) {
        const __nv_bfloat162* r = (const __nv_bfloat162*)(sH + tid * PH);
        float s = 0.f;
#pragma unroll 8
        for (int k = 0; k < DFEAT / 2; k++) {
            float2 f = __bfloat1622float2(r[k]);
            s = fmaf(f.x, f.x, s);
            s = fmaf(f.y, f.y, s);
        }
        sSq[tid] = s;
    }
    __syncthreads();

    // ---- Gram over upper-triangle tiles, round-robin per warp ----
    int lrow = lane & 15;
    int lcol8 = (lane >> 4) << 3;
    int gq = lane >> 2;        // 0..7
    int tq = lane & 3;         // 0..3
    float dsum = 0.f;

    for (int idx = w; idx < 136; idx += 16) {
        int tt = c_tile[idx];
        int i0 = (tt >> 4) * 16, j0 = (tt & 15) * 16;
        bool isDiag = (i0 == j0);

        unsigned a[8][4];
#pragma unroll
        for (int kc = 0; kc < 8; kc++) {
            unsigned ad = sHb + 2u * ((i0 + lrow) * PH + kc * 16 + lcol8);
            ldsm_x4(ad, a[kc][0], a[kc][1], a[kc][2], a[kc][3]);
        }

        float c0[4] = {0.f, 0.f, 0.f, 0.f};
        float c1[4] = {0.f, 0.f, 0.f, 0.f};
#pragma unroll
        for (int kc = 0; kc < 8; kc++) {
            unsigned bd = sHb + 2u * ((j0 + lrow) * PH + kc * 16 + lcol8);
            unsigned b0, b1, b2, b3;
            ldsm_x4(bd, b0, b1, b2, b3);
            mma_bf16(c0[0], c0[1], c0[2], c0[3], a[kc][0], a[kc][1], a[kc][2], a[kc][3], b0, b2);
            mma_bf16(c1[0], c1[1], c1[2], c1[3], a[kc][0], a[kc][1], a[kc][2], a[kc][3], b1, b3);
        }

#pragma unroll
        for (int t2 = 0; t2 < 2; t2++) {
            const float* cc = t2 ? c1 : c0;
            int jc = j0 + t2 * 8 + 2 * tq;
            float sqj0 = sSq[jc], sqj1 = sSq[jc + 1];
#pragma unroll
            for (int rh = 0; rh < 2; rh++) {
                int r = i0 + gq + rh * 8;
                float sqi = sSq[r];
                float da = sqrtf(fmaxf(fmaf(-2.f, cc[rh * 2 + 0], sqi + sqj0), 0.f) + 1e-12f);
                float db = sqrtf(fmaxf(fmaf(-2.f, cc[rh * 2 + 1], sqi + sqj1), 0.f) + 1e-12f);
                if (!isDiag) {
                    dsum += 2.f * (da + db);
                } else {
                    float wa = (jc > r) ? 2.f : ((jc == r) ? 1.f : 0.f);
                    float wb = (jc + 1 > r) ? 2.f : ((jc + 1 == r) ? 1.f : 0.f);
                    dsum = fmaf(wa, da, dsum);
                    dsum = fmaf(wb, db, dsum);
                }
                __nv_bfloat162 dd = __floats2bfloat162_rn(da, db);
                *(unsigned*)(sm + OFF_D + (r * PD + jc) * 2) = *(unsigned*)&dd;
            }
        }
    }

    dsum = warpSum(dsum);
    if (lane == 0) sRed[w] = dsum;
    __syncthreads();
    if (tid == 0) {
        float tot = 0.f;
#pragma unroll
        for (int i = 0; i < 16; i++) tot += sRed[i];
        float mean = tot * (1.0f / 65536.0f);
        sHist[256 + 16] = 1.0f / (mean + 1e-8f);
    }
    __syncthreads();
    float invm = sHist[256 + 16];

    // ---- histogram over upper triangle (weight 2 folded at reduce) ----
    unsigned long long Hc[8];
#pragma unroll
    for (int p = 0; p < 8; p++) Hc[p] = pk2(0.f, 0.f);
    const unsigned long long C4p = pk2(C_C4, C_C4);

    {
        int p = tid >> 2, q = tid & 3;
        int La = 255 - p;            // row p holds cols p+1..255
        const char* Dbase = sm + OFF_D;
        for (int c = q; c < 255; c += 4) {
            int row = (c < La) ? p : (255 - p);
            int col = (c < La) ? (p + 1 + c) : (c + 1);
            unsigned short u = *(const unsigned short*)(Dbase + (row * PD + col) * 2);
            unsigned ui = ((unsigned)u) << 16;
            float d = __uint_as_float(ui);
            float x = fminf(d * invm, 2.46f);
            accum_packed(x, Hc, C4p);
        }
    }

    // unpack, double (upper-triangle weight), add diagonal with weight 1
    float hl[16];
#pragma unroll
    for (int p = 0; p < 8; p++) {
        upk2(Hc[p], hl[2 * p], hl[2 * p + 1]);
        hl[2 * p] *= 2.f;
        hl[2 * p + 1] *= 2.f;
    }
    if (tid < 256) {
        unsigned short u = *(const unsigned short*)(sm + OFF_D + (tid * PD + tid) * 2);
        float d = __uint_as_float(((unsigned)u) << 16);
        float x = fminf(d * invm, 2.46f);
        float w0 = exp2f(K_W * x * x);
        float r0 = exp2f(fmaf(K_L, x, K_O));
        float wk = w0, rk = r0;
#pragma unroll
        for (int k = 0; k < 16; k++) {
            hl[k] += wk;
            wk *= rk;
            rk *= C_C1;
        }
    }

#pragma unroll
    for (int k = 0; k < 16; k++) {
        float v = warpSum(hl[k]);
        if (lane == 0) sHist[w * 16 + k] = v;
    }
    __syncthreads();
    if (tid < 16) {
        float s = 0.f;
#pragma unroll
        for (int ww = 0; ww < 16; ww++) s += sHist[ww * 16 + tid];
        sHist[256 + tid] = s;
    }
    __syncthreads();
    if (tid == 0) {
        float S = 0.f;
#pragma unroll
        for (int k = 0; k < 16; k++) S += sHist[256 + k];
        sHist[256 + 17] = 1.0f / (S + 1e-8f);
    }
    __syncthreads();
    if (tid < 16) g_sig[gv * KB + tid] = sHist[256 + tid] * sHist[256 + 17];
}

// ---------------------------------------------------------------------------
// NT-Xent: 32 blocks x 8 rows
// ---------------------------------------------------------------------------
__global__ void __launch_bounds__(256, 1)
kC(const float* __restrict__ z1, const float* __restrict__ z2) {
    extern __shared__ float smf[];
    float* zn = smf;
    float* sRed = smf + 256 * PITCHC;

    int tid = threadIdx.x;
    for (int t = tid; t < 2 * G * DFEAT; t += 256) {
        int row = t >> 7, k = t & 127;
        float v = (row < G) ? z1[t] : z2[t - G * DFEAT];
        zn[row * PITCHC + k] = v;
    }
    __syncthreads();
    {
        int row = tid;
        float* r = zn + row * PITCHC;
        float s = 0.f;
#pragma unroll 8
        for (int k = 0; k < DFEAT; k++) s += r[k] * r[k];
        float inv = 1.0f / (sqrtf(s) + 1e-8f);
#pragma unroll 8
        for (int k = 0; k < DFEAT; k++) r[k] *= inv;
    }
    __syncthreads();

    int w = tid >> 5, lane = tid & 31;
    int i = blockIdx.x * 8 + w;
    int label = (i < G) ? i + G : i - G;
    const float* zi = zn + i * PITCHC;

    float sims[8];
#pragma unroll
    for (int s = 0; s < 8; s++) {
        int j = lane + 32 * s;
        const float* zj = zn + j * PITCHC;
        float acc = 0.f;
        for (int k = 0; k < DFEAT; k += 4) {
            float4 a = *(const float4*)(zi + k);
            float4 b = *(const float4*)(zj + k);
            acc = fmaf(a.x, b.x, acc);
            acc = fmaf(a.y, b.y, acc);
            acc = fmaf(a.z, b.z, acc);
            acc = fmaf(a.w, b.w, acc);
        }
        float sim = acc * 2.0f;
        if (j == i) sim = -1e9f;
        sims[s] = sim;
    }

    float m = -1e30f, slab = 0.f;
#pragma unroll
    for (int s = 0; s < 8; s++) {
        m = fmaxf(m, sims[s]);
        if (lane + 32 * s == label) slab = sims[s];
    }
#pragma unroll
    for (int o = 16; o > 0; o >>= 1)
        m = fmaxf(m, __shfl_xor_sync(0xffffffffu, m, o));

    float se = 0.f;
#pragma unroll
    for (int s = 0; s < 8; s++) se += __expf(sims[s] - m);
    se = warpSum(se);
    slab = warpSum(slab);

    if (lane == 0) sRed[w] = (m + logf(se)) - slab;
    __syncthreads();
    if (tid == 0) {
        float t = 0.f;
        for (int s = 0; s < 8; s++) t += sRed[s];
        g_ntx[blockIdx.x] = t;
    }
}

// ---------------------------------------------------------------------------
__global__ void kD(float* out) {
    __shared__ float sRed[4];
    int tid = threadIdx.x;
    int w = tid >> 5, lane = tid & 31;

    float t = 0.f;
    {
        const float* a = g_sig + tid * KB;
        const float* b = g_sig + (G + tid) * KB;
#pragma unroll
        for (int k = 0; k < KB; k++) {
            float d = a[k] - b[k];
            t += d * d;
        }
        t *= (1.0f / KB);
    }
    t = warpSum(t);
    if (lane == 0) sRed[w] = t;
    __syncthreads();

    float ntx = 0.f;
    if (tid < 32) ntx = g_ntx[tid];
    ntx = warpSum(ntx);

    if (tid == 0) {
        float topo = (sRed[0] + sRed[1] + sRed[2] + sRed[3]) * (1.0f / G);
        out[0] = 0.1f * (topo + ntx * (1.0f / 256.0f));
    }
}

// ---------------------------------------------------------------------------
extern "C" void kernel_launch(void* const* d_in, const int* in_sizes, int n_in,
                              void* d_out, int out_size) {
    const float* H1 = (const float*)d_in[0];
    const float* H2 = (const float*)d_in[2];
    const float* z1 = (const float*)d_in[4];
    const float* z2 = (const float*)d_in[5];

    size_t smAB = SMEM_AB;
    size_t smC = (size_t)(256 * PITCHC + 32) * sizeof(float);
    cudaFuncSetAttribute(kAB, cudaFuncAttributeMaxDynamicSharedMemorySize, (int)smAB);
    cudaFuncSetAttribute(kC, cudaFuncAttributeMaxDynamicSharedMemorySize, (int)smC);

    kAB<<<256, 512, smAB>>>(H1, H2);
    kC<<<32, 256, smC>>>(z1, z2);
    kD<<<1, 128>>>((float*)d_out);
}